// round 1
// baseline (speedup 1.0000x reference)
#include <cuda_runtime.h>
#include <math.h>

// Problem dims (fixed by the dataset)
#define Bd 2
#define Td 2048
#define Cd 1024
#define Hd 16
#define Dd 64

// Scratch: qkv [B,T,3C] and attention output [B,T,C]
__device__ float g_qkv[(size_t)Bd * Td * 3 * Cd];
__device__ float g_att[(size_t)Bd * Td * Cd];

// ---------------------------------------------------------------------------
// SGEMM + bias: C[M,N] = A[M,K] @ B[K,N] + bias[N]
// 128x128 block tile, BK=16, 8x8 per-thread tile, 256 threads.
// ---------------------------------------------------------------------------
#define BM 128
#define BN 128
#define BK 16
#define TM 8
#define TN 8

__global__ __launch_bounds__(256) void sgemm_bias_kernel(
    const float* __restrict__ A, const float* __restrict__ B,
    const float* __restrict__ bias, float* __restrict__ C,
    int M, int N, int K)
{
    __shared__ __align__(16) float As[BK][BM];
    __shared__ __align__(16) float Bs[BK][BN];

    const int tid  = threadIdx.x;
    const int cRow = blockIdx.y * BM;
    const int cCol = blockIdx.x * BN;

    const int tCol = (tid % (BN / TN)) * TN;   // 0..120 step 8
    const int tRow = (tid / (BN / TN)) * TM;   // 0..120 step 8

    float acc[TM][TN];
    #pragma unroll
    for (int i = 0; i < TM; i++)
        #pragma unroll
        for (int j = 0; j < TN; j++) acc[i][j] = 0.0f;

    const float* Aptr = A + (size_t)cRow * K;
    const float* Bptr = B + cCol;

    for (int k0 = 0; k0 < K; k0 += BK) {
        // Load A tile (BM x BK) -> As transposed [BK][BM]
        #pragma unroll
        for (int i = 0; i < (BM * BK) / (4 * 256); i++) {     // 2 float4 / thread
            int idx = tid + i * 256;
            int r   = idx >> 2;          // / (BK/4)
            int c4  = idx & 3;           // % (BK/4)
            float4 v = *reinterpret_cast<const float4*>(Aptr + (size_t)r * K + k0 + c4 * 4);
            As[c4 * 4 + 0][r] = v.x;
            As[c4 * 4 + 1][r] = v.y;
            As[c4 * 4 + 2][r] = v.z;
            As[c4 * 4 + 3][r] = v.w;
        }
        // Load B tile (BK x BN)
        #pragma unroll
        for (int i = 0; i < (BK * BN) / (4 * 256); i++) {     // 2 float4 / thread
            int idx = tid + i * 256;
            int r   = idx >> 5;          // / (BN/4)
            int c4  = idx & 31;          // % (BN/4)
            *reinterpret_cast<float4*>(&Bs[r][c4 * 4]) =
                *reinterpret_cast<const float4*>(Bptr + (size_t)(k0 + r) * N + c4 * 4);
        }
        __syncthreads();

        #pragma unroll
        for (int kk = 0; kk < BK; kk++) {
            float regM[TM], regN[TN];
            float4 m0 = *reinterpret_cast<const float4*>(&As[kk][tRow]);
            float4 m1 = *reinterpret_cast<const float4*>(&As[kk][tRow + 4]);
            regM[0]=m0.x; regM[1]=m0.y; regM[2]=m0.z; regM[3]=m0.w;
            regM[4]=m1.x; regM[5]=m1.y; regM[6]=m1.z; regM[7]=m1.w;
            float4 n0 = *reinterpret_cast<const float4*>(&Bs[kk][tCol]);
            float4 n1 = *reinterpret_cast<const float4*>(&Bs[kk][tCol + 4]);
            regN[0]=n0.x; regN[1]=n0.y; regN[2]=n0.z; regN[3]=n0.w;
            regN[4]=n1.x; regN[5]=n1.y; regN[6]=n1.z; regN[7]=n1.w;
            #pragma unroll
            for (int i = 0; i < TM; i++)
                #pragma unroll
                for (int j = 0; j < TN; j++)
                    acc[i][j] = fmaf(regM[i], regN[j], acc[i][j]);
        }
        __syncthreads();
    }

    // Epilogue: add bias, store float4
    #pragma unroll
    for (int i = 0; i < TM; i++) {
        float* crow = C + (size_t)(cRow + tRow + i) * N + cCol + tCol;
        #pragma unroll
        for (int j = 0; j < TN; j += 4) {
            float4 o;
            o.x = acc[i][j + 0] + bias[cCol + tCol + j + 0];
            o.y = acc[i][j + 1] + bias[cCol + tCol + j + 1];
            o.z = acc[i][j + 2] + bias[cCol + tCol + j + 2];
            o.w = acc[i][j + 3] + bias[cCol + tCol + j + 3];
            *reinterpret_cast<float4*>(crow + j) = o;
        }
    }
}

// ---------------------------------------------------------------------------
// Causal flash attention.
// Grid: (T/BQ, B*H). 128 threads, one query row per thread.
// K/V tiles of 64 rows staged in SMEM; online softmax in registers.
// ---------------------------------------------------------------------------
#define BQ  128
#define BKV 64

__global__ __launch_bounds__(128) void attn_kernel()
{
    const int qt  = blockIdx.x;
    const int bh  = blockIdx.y;
    const int b   = bh / Hd;
    const int h   = bh % Hd;
    const int tid = threadIdx.x;
    const int t   = qt * BQ + tid;           // this thread's query row

    __shared__ __align__(16) float Ks[BKV][Dd];
    __shared__ __align__(16) float Vs[BKV][Dd];

    const float* qkv_b = g_qkv + (size_t)b * Td * 3 * Cd;
    const int qoff = h * Dd;
    const int koff = Cd + h * Dd;
    const int voff = 2 * Cd + h * Dd;

    // Load this row's Q, pre-scaled by 1/sqrt(D)
    float q[Dd];
    {
        const float* qrow = qkv_b + (size_t)t * 3 * Cd + qoff;
        const float scale = 0.125f;   // 1/sqrt(64)
        #pragma unroll
        for (int d4 = 0; d4 < Dd / 4; d4++) {
            float4 v = *reinterpret_cast<const float4*>(qrow + d4 * 4);
            q[d4 * 4 + 0] = v.x * scale;
            q[d4 * 4 + 1] = v.y * scale;
            q[d4 * 4 + 2] = v.z * scale;
            q[d4 * 4 + 3] = v.w * scale;
        }
    }

    float m = -INFINITY, l = 0.0f;
    float o[Dd];
    #pragma unroll
    for (int d = 0; d < Dd; d++) o[d] = 0.0f;

    // Key tiles covering 0 .. (block max row), uniform across the block
    const int nkt = (qt * BQ + BQ + BKV - 1) / BKV;

    for (int kt = 0; kt < nkt; kt++) {
        __syncthreads();
        // Stage K/V tile: 64 rows x 16 float4 = 1024 f4, 8 per thread
        #pragma unroll
        for (int i = 0; i < 8; i++) {
            int idx = tid + i * 128;
            int r   = idx >> 4;
            int c4  = idx & 15;
            const float* src = qkv_b + (size_t)(kt * BKV + r) * 3 * Cd;
            *reinterpret_cast<float4*>(&Ks[r][c4 * 4]) =
                *reinterpret_cast<const float4*>(src + koff + c4 * 4);
            *reinterpret_cast<float4*>(&Vs[r][c4 * 4]) =
                *reinterpret_cast<const float4*>(src + voff + c4 * 4);
        }
        __syncthreads();

        // Number of causally-valid keys in this tile for my row
        int jmax = t - kt * BKV + 1;
        if (jmax > BKV) jmax = BKV;

        for (int j = 0; j < jmax; j++) {
            // dot(q, K[j]) with 4 partial sums (break the serial FMA chain)
            float s0 = 0.f, s1 = 0.f, s2 = 0.f, s3 = 0.f;
            #pragma unroll
            for (int d = 0; d < Dd; d += 4) {
                float4 kv = *reinterpret_cast<const float4*>(&Ks[j][d]);
                s0 = fmaf(q[d + 0], kv.x, s0);
                s1 = fmaf(q[d + 1], kv.y, s1);
                s2 = fmaf(q[d + 2], kv.z, s2);
                s3 = fmaf(q[d + 3], kv.w, s3);
            }
            float s = (s0 + s1) + (s2 + s3);

            float mn = fmaxf(m, s);
            float sc = __expf(m - mn);   // 1.0 when m unchanged
            float p  = __expf(s - mn);
            l = fmaf(l, sc, p);
            m = mn;
            #pragma unroll
            for (int d = 0; d < Dd; d += 4) {
                float4 vv = *reinterpret_cast<const float4*>(&Vs[j][d]);
                o[d + 0] = fmaf(o[d + 0], sc, p * vv.x);
                o[d + 1] = fmaf(o[d + 1], sc, p * vv.y);
                o[d + 2] = fmaf(o[d + 2], sc, p * vv.z);
                o[d + 3] = fmaf(o[d + 3], sc, p * vv.w);
            }
        }
    }

    // Normalize and write y_att[b, t, h*D + d]
    const float inv = 1.0f / l;
    float* dst = g_att + ((size_t)b * Td + t) * Cd + h * Dd;
    #pragma unroll
    for (int d = 0; d < Dd; d += 4) {
        float4 ov;
        ov.x = o[d + 0] * inv;
        ov.y = o[d + 1] * inv;
        ov.z = o[d + 2] * inv;
        ov.w = o[d + 3] * inv;
        *reinterpret_cast<float4*>(dst + d) = ov;
    }
}

// ---------------------------------------------------------------------------
// Launch
// ---------------------------------------------------------------------------
extern "C" void kernel_launch(void* const* d_in, const int* in_sizes, int n_in,
                              void* d_out, int out_size)
{
    const float* x      = (const float*)d_in[0];
    // d_in[1] = attn_mask: tril by construction, causality handled structurally
    const float* W_attn = (const float*)d_in[2];
    const float* b_attn = (const float*)d_in[3];
    const float* W_proj = (const float*)d_in[4];
    const float* b_proj = (const float*)d_in[5];
    float* out = (float*)d_out;

    float* qkv = nullptr;
    float* att = nullptr;
    cudaGetSymbolAddress((void**)&qkv, g_qkv);
    cudaGetSymbolAddress((void**)&att, g_att);

    const int M = Bd * Td;     // 4096

    // 1) QKV = x @ W_attn + b_attn : [4096,1024] x [1024,3072]
    {
        dim3 grid((3 * Cd) / BN, M / BM);
        sgemm_bias_kernel<<<grid, 256>>>(x, W_attn, b_attn, qkv, M, 3 * Cd, Cd);
    }
    // 2) causal attention per (b,h)
    {
        dim3 grid(Td / BQ, Bd * Hd);
        attn_kernel<<<grid, 128>>>();
    }
    // 3) out = att @ W_proj + b_proj : [4096,1024] x [1024,1024]
    {
        dim3 grid(Cd / BN, M / BM);
        sgemm_bias_kernel<<<grid, 256>>>(att, W_proj, b_proj, out, M, Cd, Cd);
    }
}

// round 2
// speedup vs baseline: 1.4553x; 1.4553x over previous
#include <cuda_runtime.h>
#include <math.h>
#include <stdint.h>

// Problem dims (fixed by the dataset)
#define Bd 2
#define Td 2048
#define Cd 1024
#define Hd 16
#define Dd 64

// Scratch: qkv [B,T,3C] and attention output [B,T,C]
__device__ float g_qkv[(size_t)Bd * Td * 3 * Cd];
__device__ float g_att[(size_t)Bd * Td * Cd];

// ---------------------------------------------------------------------------
// TF32 tensor-core GEMM + bias: C[M,N] = A[M,K] @ B[K,N] + bias[N]
// 128x128 block tile, BK=32, 8 warps (2x4), 64x32 warp tile, m16n8k8 mma.
// ---------------------------------------------------------------------------
#define GBM 128
#define GBN 128
#define GBK 32

__device__ __forceinline__ uint32_t f2tf32(float x) {
    uint32_t r;
    asm("cvt.rna.tf32.f32 %0, %1;" : "=r"(r) : "f"(x));
    return r;
}

__global__ __launch_bounds__(256) void gemm_tf32_bias(
    const float* __restrict__ A, const float* __restrict__ B,
    const float* __restrict__ bias, float* __restrict__ C,
    int M, int N, int K)
{
    // As: [row][k], stride 36 -> conflict-free frag loads (bank = 4*row + k)
    // Bs: [k][n],  stride 136 -> conflict-free frag loads (bank = 8*k + n)
    __shared__ __align__(16) float As[GBM][GBK + 4];
    __shared__ __align__(16) float Bs[GBK][GBN + 8];

    const int tid  = threadIdx.x;
    const int warp = tid >> 5;
    const int lane = tid & 31;
    const int wm = warp >> 2;          // 0..1
    const int wn = warp & 3;           // 0..3
    const int g  = lane >> 2;          // 0..7
    const int cc = lane & 3;           // 0..3

    const int row0 = blockIdx.y * GBM;
    const int col0 = blockIdx.x * GBN;

    float acc[4][4][4];
    #pragma unroll
    for (int mt = 0; mt < 4; mt++)
        #pragma unroll
        for (int nt = 0; nt < 4; nt++)
            #pragma unroll
            for (int q = 0; q < 4; q++) acc[mt][nt][q] = 0.0f;

    for (int k0 = 0; k0 < K; k0 += GBK) {
        // A tile: 128 rows x 32 k -> 1024 float4, 4 per thread
        #pragma unroll
        for (int i = 0; i < 4; i++) {
            int idx = tid + i * 256;
            int r   = idx >> 3;        // 0..127
            int c4  = idx & 7;         // 0..7
            float4 v = *reinterpret_cast<const float4*>(
                A + (size_t)(row0 + r) * K + k0 + c4 * 4);
            float4 w;
            w.x = __uint_as_float(f2tf32(v.x));
            w.y = __uint_as_float(f2tf32(v.y));
            w.z = __uint_as_float(f2tf32(v.z));
            w.w = __uint_as_float(f2tf32(v.w));
            *reinterpret_cast<float4*>(&As[r][c4 * 4]) = w;
        }
        // B tile: 32 k x 128 n -> 1024 float4, 4 per thread
        #pragma unroll
        for (int i = 0; i < 4; i++) {
            int idx = tid + i * 256;
            int r   = idx >> 5;        // k row 0..31
            int c4  = idx & 31;        // 0..31
            float4 v = *reinterpret_cast<const float4*>(
                B + (size_t)(k0 + r) * N + col0 + c4 * 4);
            float4 w;
            w.x = __uint_as_float(f2tf32(v.x));
            w.y = __uint_as_float(f2tf32(v.y));
            w.z = __uint_as_float(f2tf32(v.z));
            w.w = __uint_as_float(f2tf32(v.w));
            *reinterpret_cast<float4*>(&Bs[r][c4 * 4]) = w;
        }
        __syncthreads();

        #pragma unroll
        for (int kk = 0; kk < GBK / 8; kk++) {
            const int kc = kk * 8 + cc;
            // A fragments: 4 m-tiles
            uint32_t a[4][4];
            #pragma unroll
            for (int mt = 0; mt < 4; mt++) {
                int r = wm * 64 + mt * 16 + g;
                a[mt][0] = __float_as_uint(As[r][kc]);
                a[mt][1] = __float_as_uint(As[r + 8][kc]);
                a[mt][2] = __float_as_uint(As[r][kc + 4]);
                a[mt][3] = __float_as_uint(As[r + 8][kc + 4]);
            }
            // B fragments: 4 n-tiles
            uint32_t b[4][2];
            #pragma unroll
            for (int nt = 0; nt < 4; nt++) {
                int n = wn * 32 + nt * 8 + g;
                b[nt][0] = __float_as_uint(Bs[kc][n]);
                b[nt][1] = __float_as_uint(Bs[kc + 4][n]);
            }
            #pragma unroll
            for (int mt = 0; mt < 4; mt++)
                #pragma unroll
                for (int nt = 0; nt < 4; nt++) {
                    asm volatile(
                        "mma.sync.aligned.m16n8k8.row.col.f32.tf32.tf32.f32 "
                        "{%0,%1,%2,%3}, {%4,%5,%6,%7}, {%8,%9}, {%0,%1,%2,%3};"
                        : "+f"(acc[mt][nt][0]), "+f"(acc[mt][nt][1]),
                          "+f"(acc[mt][nt][2]), "+f"(acc[mt][nt][3])
                        : "r"(a[mt][0]), "r"(a[mt][1]), "r"(a[mt][2]), "r"(a[mt][3]),
                          "r"(b[nt][0]), "r"(b[nt][1]));
                }
        }
        __syncthreads();
    }

    // Epilogue: bias + store (float2 per fragment half)
    #pragma unroll
    for (int mt = 0; mt < 4; mt++) {
        int r = row0 + wm * 64 + mt * 16 + g;
        #pragma unroll
        for (int nt = 0; nt < 4; nt++) {
            int n = col0 + wn * 32 + nt * 8 + cc * 2;
            float2 bb = *reinterpret_cast<const float2*>(bias + n);
            float2 o0, o1;
            o0.x = acc[mt][nt][0] + bb.x;
            o0.y = acc[mt][nt][1] + bb.y;
            o1.x = acc[mt][nt][2] + bb.x;
            o1.y = acc[mt][nt][3] + bb.y;
            *reinterpret_cast<float2*>(C + (size_t)r * N + n)       = o0;
            *reinterpret_cast<float2*>(C + (size_t)(r + 8) * N + n) = o1;
        }
    }
}

// ---------------------------------------------------------------------------
// Causal flash attention, deferred-rescale (16-key chunks).
// Grid: (T/BQ, B*H). 128 threads, one query row per thread.
// ---------------------------------------------------------------------------
#define BQ  128
#define BKV 64
#define CHK 16

__global__ __launch_bounds__(128) void attn_kernel()
{
    const int qt  = blockIdx.x;
    const int bh  = blockIdx.y;
    const int b   = bh / Hd;
    const int h   = bh % Hd;
    const int tid = threadIdx.x;
    const int t   = qt * BQ + tid;

    __shared__ __align__(16) float Ks[BKV][Dd];
    __shared__ __align__(16) float Vs[BKV][Dd];

    const float* qkv_b = g_qkv + (size_t)b * Td * 3 * Cd;
    const int koff = Cd + h * Dd;
    const int voff = 2 * Cd + h * Dd;

    float q[Dd];
    {
        const float* qrow = qkv_b + (size_t)t * 3 * Cd + h * Dd;
        const float scale = 0.125f;   // 1/sqrt(64)
        #pragma unroll
        for (int d4 = 0; d4 < Dd / 4; d4++) {
            float4 v = *reinterpret_cast<const float4*>(qrow + d4 * 4);
            q[d4 * 4 + 0] = v.x * scale;
            q[d4 * 4 + 1] = v.y * scale;
            q[d4 * 4 + 2] = v.z * scale;
            q[d4 * 4 + 3] = v.w * scale;
        }
    }

    float m = -INFINITY, l = 0.0f;
    float o[Dd];
    #pragma unroll
    for (int d = 0; d < Dd; d++) o[d] = 0.0f;

    const int nkt = (qt * BQ + BQ + BKV - 1) / BKV;

    for (int kt = 0; kt < nkt; kt++) {
        __syncthreads();
        #pragma unroll
        for (int i = 0; i < 8; i++) {
            int idx = tid + i * 128;
            int r   = idx >> 4;
            int c4  = idx & 15;
            const float* src = qkv_b + (size_t)(kt * BKV + r) * 3 * Cd;
            *reinterpret_cast<float4*>(&Ks[r][c4 * 4]) =
                *reinterpret_cast<const float4*>(src + koff + c4 * 4);
            *reinterpret_cast<float4*>(&Vs[r][c4 * 4]) =
                *reinterpret_cast<const float4*>(src + voff + c4 * 4);
        }
        __syncthreads();

        int jmax = t - kt * BKV + 1;
        if (jmax > BKV) jmax = BKV;

        for (int jb = 0; jb < jmax; jb += CHK) {
            const int cnt = min(CHK, jmax - jb);

            // scores for this chunk
            float s[CHK];
            float cmax = -INFINITY;
            #pragma unroll
            for (int jj = 0; jj < CHK; jj++) {
                if (jj < cnt) {
                    const int j = jb + jj;
                    float s0 = 0.f, s1 = 0.f, s2 = 0.f, s3 = 0.f;
                    #pragma unroll
                    for (int d = 0; d < Dd; d += 4) {
                        float4 kv = *reinterpret_cast<const float4*>(&Ks[j][d]);
                        s0 = fmaf(q[d + 0], kv.x, s0);
                        s1 = fmaf(q[d + 1], kv.y, s1);
                        s2 = fmaf(q[d + 2], kv.z, s2);
                        s3 = fmaf(q[d + 3], kv.w, s3);
                    }
                    s[jj] = (s0 + s1) + (s2 + s3);
                    cmax = fmaxf(cmax, s[jj]);
                }
            }

            // one rescale per chunk
            const float mn = fmaxf(m, cmax);
            const float sc = __expf(m - mn);
            m = mn;
            l *= sc;
            #pragma unroll
            for (int d = 0; d < Dd; d++) o[d] *= sc;

            // accumulate
            #pragma unroll
            for (int jj = 0; jj < CHK; jj++) {
                if (jj < cnt) {
                    const int j = jb + jj;
                    const float p = __expf(s[jj] - mn);
                    l += p;
                    #pragma unroll
                    for (int d = 0; d < Dd; d += 4) {
                        float4 vv = *reinterpret_cast<const float4*>(&Vs[j][d]);
                        o[d + 0] = fmaf(p, vv.x, o[d + 0]);
                        o[d + 1] = fmaf(p, vv.y, o[d + 1]);
                        o[d + 2] = fmaf(p, vv.z, o[d + 2]);
                        o[d + 3] = fmaf(p, vv.w, o[d + 3]);
                    }
                }
            }
        }
    }

    const float inv = 1.0f / l;
    float* dst = g_att + ((size_t)b * Td + t) * Cd + h * Dd;
    #pragma unroll
    for (int d = 0; d < Dd; d += 4) {
        float4 ov;
        ov.x = o[d + 0] * inv;
        ov.y = o[d + 1] * inv;
        ov.z = o[d + 2] * inv;
        ov.w = o[d + 3] * inv;
        *reinterpret_cast<float4*>(dst + d) = ov;
    }
}

// ---------------------------------------------------------------------------
// Launch
// ---------------------------------------------------------------------------
extern "C" void kernel_launch(void* const* d_in, const int* in_sizes, int n_in,
                              void* d_out, int out_size)
{
    const float* x      = (const float*)d_in[0];
    // d_in[1] = attn_mask: tril by construction; causality handled structurally
    const float* W_attn = (const float*)d_in[2];
    const float* b_attn = (const float*)d_in[3];
    const float* W_proj = (const float*)d_in[4];
    const float* b_proj = (const float*)d_in[5];
    float* out = (float*)d_out;

    float* qkv = nullptr;
    float* att = nullptr;
    cudaGetSymbolAddress((void**)&qkv, g_qkv);
    cudaGetSymbolAddress((void**)&att, g_att);

    const int M = Bd * Td;     // 4096

    // 1) QKV = x @ W_attn + b_attn : [4096,1024] x [1024,3072]
    {
        dim3 grid((3 * Cd) / GBN, M / GBM);
        gemm_tf32_bias<<<grid, 256>>>(x, W_attn, b_attn, qkv, M, 3 * Cd, Cd);
    }
    // 2) causal attention per (b,h)
    {
        dim3 grid(Td / BQ, Bd * Hd);
        attn_kernel<<<grid, 128>>>();
    }
    // 3) out = att @ W_proj + b_proj : [4096,1024] x [1024,1024]
    {
        dim3 grid(Cd / GBN, M / GBM);
        gemm_tf32_bias<<<grid, 256>>>(att, W_proj, b_proj, out, M, Cd, Cd);
    }
}